// round 2
// baseline (speedup 1.0000x reference)
#include <cuda_runtime.h>
#include <math.h>
#include <stdint.h>

// ---------------- problem constants (static per reference) ----------------
#define BSZ   8
#define NQ    4096
#define CDIM  256
#define NHEAD 8
#define NPT   4
#define NLVL  6
#define NVAL  10752
#define DHEAD 32          // CDIM / NHEAD
#define NOFF  384         // NHEAD*NLVL*NPT*2
#define NATT  192         // NHEAD*NLVL*NPT

// ---------------- device scratch (static, no allocation) ------------------
__device__ float g_vproj[(size_t)BSZ * NVAL * CDIM];  // value @ W_val + b_val
__device__ float g_off  [(size_t)BSZ * NQ   * NOFF];  // q @ W_off + b_off
__device__ float g_attn [(size_t)BSZ * NQ   * NATT];  // q @ W_attn + b_attn
__device__ float g_ms   [(size_t)BSZ * NQ   * CDIM];  // deform-attn output

__constant__ int c_H[NLVL] = {64, 32, 16, 64, 32, 16};
__constant__ int c_W[NLVL] = {64, 32, 16, 64, 32, 16};
__constant__ int c_S[NLVL] = {0, 4096, 5120, 5376, 9472, 10496};

// packed f32x2 FMA (SASS FFMA2): two independent fp32 FMAs per fma-pipe issue
__device__ __forceinline__ void fma2(unsigned long long& d,
                                     unsigned long long a,
                                     unsigned long long b)
{
    asm("fma.rn.f32x2 %0, %1, %2, %0;" : "+l"(d) : "l"(a), "l"(b));
}
__device__ __forceinline__ float f2lo(unsigned long long u) {
    return __uint_as_float((unsigned)(u & 0xffffffffu));
}
__device__ __forceinline__ float f2hi(unsigned long long u) {
    return __uint_as_float((unsigned)(u >> 32));
}

// ---------------- tiled fp32 GEMM: C[M,N] = (A (+A2)) @ B + bias (+resid) --
// BM=128, BN=64, BK=16, 256 threads. Thread tile 8 rows x 4 cols, computed as
// 4 row-PAIRS x 4 cols of packed f32x2 FMAs. Bs stored value-duplicated so the
// b operand pair (b,b) comes straight from an LDS with no packing ALU.
template <bool ADD_A2, bool RESID>
__global__ __launch_bounds__(256)
void gemm_kernel(const float* __restrict__ A, const float* __restrict__ A2,
                 const float* __restrict__ B, const float* __restrict__ bias,
                 const float* __restrict__ resid, float* __restrict__ C,
                 int M, int N, int K)
{
    const int BM = 128, BN = 64, BK = 16;
    __shared__ float As[BK][BM];
    __shared__ float Bs[BK][BN * 2];   // duplicated: [.., b_c, b_c, ..]

    const int tid = threadIdx.x;
    const int bm = blockIdx.x * BM;
    const int bn = blockIdx.y * BN;
    const int ty = tid >> 4;          // 0..15 -> 8 rows each
    const int tx = tid & 15;          // 0..15 -> 4 cols each

    const int ar = tid >> 2;          // 0..63 (rows ar, ar+64)
    const int ac = (tid & 3) * 4;     // 0,4,8,12
    const int br = tid >> 4;          // 0..15
    const int bc = (tid & 15) * 4;    // 0..60

    unsigned long long acc[4][4];     // [row-pair][col] packed fp32x2
#pragma unroll
    for (int i = 0; i < 4; i++)
#pragma unroll
        for (int j = 0; j < 4; j++) acc[i][j] = 0ULL;

    for (int k0 = 0; k0 < K; k0 += BK) {
#pragma unroll
        for (int rr = 0; rr < 2; rr++) {
            const int row = ar + rr * 64;
            float4 v = *(const float4*)(A + (size_t)(bm + row) * K + k0 + ac);
            if (ADD_A2) {
                float4 u = *(const float4*)(A2 + (size_t)(bm + row) * K + k0 + ac);
                v.x += u.x; v.y += u.y; v.z += u.z; v.w += u.w;
            }
            As[ac + 0][row] = v.x;
            As[ac + 1][row] = v.y;
            As[ac + 2][row] = v.z;
            As[ac + 3][row] = v.w;
        }
        {
            float4 v = *(const float4*)(B + (size_t)(k0 + br) * N + bn + bc);
            float* dst = &Bs[br][bc * 2];
            *(float4*)(dst + 0) = make_float4(v.x, v.x, v.y, v.y);
            *(float4*)(dst + 4) = make_float4(v.z, v.z, v.w, v.w);
        }
        __syncthreads();

#pragma unroll
        for (int k = 0; k < BK; k++) {
            const ulonglong2* pa =
                (const ulonglong2*)(&As[k][ty * 8]);
            ulonglong2 a01 = pa[0], a23 = pa[1];
            const ulonglong2* pb =
                (const ulonglong2*)(&Bs[k][tx * 8]);
            ulonglong2 b01 = pb[0], b23 = pb[1];
            unsigned long long a[4] = {a01.x, a01.y, a23.x, a23.y};
            unsigned long long b[4] = {b01.x, b01.y, b23.x, b23.y};
#pragma unroll
            for (int ip = 0; ip < 4; ip++)
#pragma unroll
                for (int j = 0; j < 4; j++)
                    fma2(acc[ip][j], a[ip], b[j]);
        }
        __syncthreads();
    }

    const float4 bv = *(const float4*)(bias + bn + tx * 4);
#pragma unroll
    for (int ip = 0; ip < 4; ip++) {
#pragma unroll
        for (int half = 0; half < 2; half++) {
            const int row = bm + ty * 8 + ip * 2 + half;
            float4 o;
            o.x = (half ? f2hi(acc[ip][0]) : f2lo(acc[ip][0])) + bv.x;
            o.y = (half ? f2hi(acc[ip][1]) : f2lo(acc[ip][1])) + bv.y;
            o.z = (half ? f2hi(acc[ip][2]) : f2lo(acc[ip][2])) + bv.z;
            o.w = (half ? f2hi(acc[ip][3]) : f2lo(acc[ip][3])) + bv.w;
            if (RESID) {
                float4 r = *(const float4*)(resid + (size_t)row * N + bn + tx * 4);
                o.x += r.x; o.y += r.y; o.z += r.z; o.w += r.w;
            }
            *(float4*)(C + (size_t)row * N + bn + tx * 4) = o;
        }
    }
}

// ---------------- sampling kernel: one warp per (b, q, head) ----------------
// Phase 1: lanes 0..23 (one per level/point) do warp softmax + compute the 4
// bilinear corner indices/weights, stash them packed (idx,u32(w)) in smem.
// Phase 2: 4 corner-groups x 8 lanes; per point j one LDS.64 (broadcast) +
// one LDG.128 (float4 slice of the 32-dim head vector) + 4 FMA. Butterfly
// reduce across corner groups at the end.
__global__ __launch_bounds__(256)
void sample_kernel(const float* __restrict__ refp, float* __restrict__ ms)
{
    __shared__ unsigned long long sm_iw[8][24][4];   // [warp][point][corner]

    const int wslot = threadIdx.x >> 5;
    const int warp = blockIdx.x * 8 + wslot;
    const int lane = threadIdx.x & 31;
    const int h  = warp & 7;
    const int bq = warp >> 3;          // b*NQ + q
    const int b  = bq >> 12;           // NQ = 4096

    // ---- softmax over the 24 (level,point) logits ----
    float a = -INFINITY;
    if (lane < 24) a = g_attn[(size_t)bq * NATT + h * 24 + lane];
    float m = a;
#pragma unroll
    for (int s = 16; s; s >>= 1) m = fmaxf(m, __shfl_xor_sync(0xffffffffu, m, s));
    float e = (lane < 24) ? __expf(a - m) : 0.f;
    float ssum = e;
#pragma unroll
    for (int s = 16; s; s >>= 1) ssum += __shfl_xor_sync(0xffffffffu, ssum, s);
    const float aw = e / ssum;

    if (lane < 24) {
        const int l = lane >> 2;
        const int p = lane & 3;
        const int H = c_H[l], W = c_W[l], S = c_S[l];
        const size_t ob = (size_t)bq * NOFF + (((h * NLVL + l) * NPT + p) << 1);
        const float offx = g_off[ob + 0];
        const float offy = g_off[ob + 1];
        const size_t rb = ((size_t)bq * NLVL + l) << 1;
        const float rx = refp[rb + 0];
        const float ry = refp[rb + 1];
        // offset normalizer cancels: x = ref_x*W + off_x - 0.5
        const float x = rx * (float)W + offx - 0.5f;
        const float y = ry * (float)H + offy - 0.5f;
        const float xf = floorf(x), yf = floorf(y);
        const float lx = x - xf, ly = y - yf;
        const int ix = (int)xf, iy = (int)yf;
        const bool vx0 = (ix     >= 0) && (ix     < W);
        const bool vx1 = (ix + 1 >= 0) && (ix + 1 < W);
        const bool vy0 = (iy     >= 0) && (iy     < H);
        const bool vy1 = (iy + 1 >= 0) && (iy + 1 < H);
        const int cx0 = min(max(ix, 0), W - 1);
        const int cx1 = min(max(ix + 1, 0), W - 1);
        const int cy0 = min(max(iy, 0), H - 1);
        const int cy1 = min(max(iy + 1, 0), H - 1);
        const int i00 = S + cy0 * W + cx0;
        const int i01 = S + cy0 * W + cx1;
        const int i10 = S + cy1 * W + cx0;
        const int i11 = S + cy1 * W + cx1;
        const float w00 = aw * (1.f - lx) * (1.f - ly) * (float)(vx0 && vy0);
        const float w01 = aw * lx         * (1.f - ly) * (float)(vx1 && vy0);
        const float w10 = aw * (1.f - lx) * ly         * (float)(vx0 && vy1);
        const float w11 = aw * lx         * ly         * (float)(vx1 && vy1);
        sm_iw[wslot][lane][0] =
            (unsigned long long)(unsigned)i00 | ((unsigned long long)__float_as_uint(w00) << 32);
        sm_iw[wslot][lane][1] =
            (unsigned long long)(unsigned)i01 | ((unsigned long long)__float_as_uint(w01) << 32);
        sm_iw[wslot][lane][2] =
            (unsigned long long)(unsigned)i10 | ((unsigned long long)__float_as_uint(w10) << 32);
        sm_iw[wslot][lane][3] =
            (unsigned long long)(unsigned)i11 | ((unsigned long long)__float_as_uint(w11) << 32);
    }
    __syncwarp();

    // ---- gather: corner group g = lane>>3, dim slice li = lane&7 ----
    const int g  = lane >> 3;
    const int li = lane & 7;
    const float* __restrict__ vb =
        g_vproj + (size_t)b * NVAL * CDIM + h * DHEAD + li * 4;

    float4 acc = make_float4(0.f, 0.f, 0.f, 0.f);
#pragma unroll
    for (int j = 0; j < 24; j++) {
        const unsigned long long u = sm_iw[wslot][j][g];
        const int   idx = (int)(unsigned)(u & 0xffffffffu);
        const float w   = __uint_as_float((unsigned)(u >> 32));
        const float4 v = *(const float4*)(vb + (size_t)idx * CDIM);
        acc.x = fmaf(w, v.x, acc.x);
        acc.y = fmaf(w, v.y, acc.y);
        acc.z = fmaf(w, v.z, acc.z);
        acc.w = fmaf(w, v.w, acc.w);
    }

    // reduce the 4 corner groups (xor over lane bits 3 and 4)
#pragma unroll
    for (int s = 8; s <= 16; s <<= 1) {
        acc.x += __shfl_xor_sync(0xffffffffu, acc.x, s);
        acc.y += __shfl_xor_sync(0xffffffffu, acc.y, s);
        acc.z += __shfl_xor_sync(0xffffffffu, acc.z, s);
        acc.w += __shfl_xor_sync(0xffffffffu, acc.w, s);
    }
    if (lane < 8)
        *(float4*)(ms + (size_t)bq * CDIM + h * DHEAD + lane * 4) = acc;
}

// ---------------- launch ----------------
extern "C" void kernel_launch(void* const* d_in, const int* in_sizes, int n_in,
                              void* d_out, int out_size)
{
    const float* query  = (const float*)d_in[0];
    const float* qpos   = (const float*)d_in[1];
    const float* value  = (const float*)d_in[2];
    const float* refp   = (const float*)d_in[3];
    // d_in[4] = spatial_shapes (static, hardcoded)
    const float* W_off  = (const float*)d_in[5];
    const float* b_off  = (const float*)d_in[6];
    const float* W_attn = (const float*)d_in[7];
    const float* b_attn = (const float*)d_in[8];
    const float* W_val  = (const float*)d_in[9];
    const float* b_val  = (const float*)d_in[10];
    const float* W_out  = (const float*)d_in[11];
    const float* b_out  = (const float*)d_in[12];
    float* out = (float*)d_out;

    float *vproj, *offr, *attnr, *msb;
    cudaGetSymbolAddress((void**)&vproj, g_vproj);
    cudaGetSymbolAddress((void**)&offr,  g_off);
    cudaGetSymbolAddress((void**)&attnr, g_attn);
    cudaGetSymbolAddress((void**)&msb,   g_ms);

    const int MQ = BSZ * NQ;      // 32768
    const int MV = BSZ * NVAL;    // 86016

    // 1) value projection: [MV,256] @ [256,256] + b_val
    gemm_kernel<false, false><<<dim3(MV / 128, CDIM / 64), 256>>>(
        value, nullptr, W_val, b_val, nullptr, vproj, MV, CDIM, CDIM);

    // 2) offsets: (query+qpos) @ W_off + b_off  -> [MQ,384]
    gemm_kernel<true, false><<<dim3(MQ / 128, NOFF / 64), 256>>>(
        query, qpos, W_off, b_off, nullptr, offr, MQ, NOFF, CDIM);

    // 3) attention logits: (query+qpos) @ W_attn + b_attn -> [MQ,192]
    gemm_kernel<true, false><<<dim3(MQ / 128, NATT / 64), 256>>>(
        query, qpos, W_attn, b_attn, nullptr, attnr, MQ, NATT, CDIM);

    // 4) softmax + bilinear sampling -> g_ms [MQ,256]
    sample_kernel<<<(BSZ * NQ * NHEAD) / 8, 256>>>(refp, msb);

    // 5) output projection + residual: g_ms @ W_out + b_out + query
    gemm_kernel<false, true><<<dim3(MQ / 128, CDIM / 64), 256>>>(
        msb, nullptr, W_out, b_out, query, out, MQ, CDIM, CDIM);
}

// round 6
// speedup vs baseline: 2.4970x; 2.4970x over previous
#include <cuda_runtime.h>
#include <cuda_bf16.h>
#include <math.h>
#include <stdint.h>

// ---------------- problem constants (static per reference) ----------------
#define BSZ   8
#define NQ    4096
#define CDIM  256
#define NHEAD 8
#define NPT   4
#define NLVL  6
#define NVAL  10752
#define DHEAD 32
#define NOFF  384
#define NATT  192
#define NQA   576          // NOFF + NATT fused GEMM width
#define NWT   1088         // 256 (val) + 576 (off|attn) + 256 (out)

// ---------------- device scratch (static, no allocation) ------------------
__device__ float g_vproj[(size_t)BSZ * NVAL * CDIM];
__device__ float g_qa   [(size_t)BSZ * NQ   * NQA];   // [off(384) | attn(192)]
__device__ float g_ms   [(size_t)BSZ * NQ   * CDIM];
__device__ __nv_bfloat16 g_Wt_hi[NWT * CDIM];         // all weights^T, bf16 hi
__device__ __nv_bfloat16 g_Wt_lo[NWT * CDIM];         // all weights^T, bf16 lo
__device__ float g_bias[NWT];

__constant__ int c_H[NLVL] = {64, 32, 16, 64, 32, 16};
__constant__ int c_W[NLVL] = {64, 32, 16, 64, 32, 16};
__constant__ int c_S[NLVL] = {0, 4096, 5120, 5376, 9472, 10496};

// ---------------- small helpers -------------------------------------------
__device__ __forceinline__ uint32_t smem_u32(const void* p) {
    uint32_t a;
    asm("{ .reg .u64 t; cvta.to.shared.u64 t, %1; cvt.u32.u64 %0, t; }"
        : "=r"(a) : "l"(p));
    return a;
}
__device__ __forceinline__ void ldsm_x4(uint32_t* r, uint32_t addr) {
    asm volatile("ldmatrix.sync.aligned.m8n8.x4.shared.b16 {%0,%1,%2,%3}, [%4];"
                 : "=r"(r[0]), "=r"(r[1]), "=r"(r[2]), "=r"(r[3]) : "r"(addr));
}
__device__ __forceinline__ void mma_bf16(float* c, const uint32_t* a,
                                         const uint32_t* b) {
    asm volatile(
        "mma.sync.aligned.m16n8k16.row.col.f32.bf16.bf16.f32 "
        "{%0,%1,%2,%3}, {%4,%5,%6,%7}, {%8,%9}, {%0,%1,%2,%3};"
        : "+f"(c[0]), "+f"(c[1]), "+f"(c[2]), "+f"(c[3])
        : "r"(a[0]), "r"(a[1]), "r"(a[2]), "r"(a[3]), "r"(b[0]), "r"(b[1]));
}
__device__ __forceinline__ uint32_t pack_bf16(float x, float y) {
    __nv_bfloat162 t = __halves2bfloat162(__float2bfloat16_rn(x),
                                          __float2bfloat16_rn(y));
    return *(uint32_t*)&t;
}

// ============== weight transpose + bf16 hi/lo split (one-time prep) ========
// n = blockIdx.x (0..1087), k = threadIdx.x (0..255)
__global__ void prep_w_kernel(const float* __restrict__ W_val,
                              const float* __restrict__ b_val,
                              const float* __restrict__ W_off,
                              const float* __restrict__ b_off,
                              const float* __restrict__ W_attn,
                              const float* __restrict__ b_attn,
                              const float* __restrict__ W_out,
                              const float* __restrict__ b_out)
{
    const int n = blockIdx.x;
    const int k = threadIdx.x;
    float x, bb;
    if (n < 256)      { x = W_val[k * 256 + n];          bb = b_val[n]; }
    else if (n < 832) {
        const int m = n - 256;
        if (m < 384)  { x = W_off[k * 384 + m];          bb = b_off[m]; }
        else          { x = W_attn[k * 192 + (m - 384)]; bb = b_attn[m - 384]; }
    }
    else              { x = W_out[k * 256 + (n - 832)];  bb = b_out[n - 832]; }
    const __nv_bfloat16 hi = __float2bfloat16_rn(x);
    const __nv_bfloat16 lo = __float2bfloat16_rn(x - __bfloat162float(hi));
    g_Wt_hi[n * CDIM + k] = hi;
    g_Wt_lo[n * CDIM + k] = lo;
    if (k == 0) g_bias[n] = bb;
}

// ============== bf16-split HMMA GEMM: C = (A (+A2)) @ B + bias (+resid) ====
// BM=128, BN=64, BK=32, 256 threads (8 warps, 4x2 warp grid, 32x32 per warp).
// B comes pre-transposed/split as bf16 [N][K] rows. A is fp32, split on the
// fly. D = Ah*Bh + Ah*Bl + Al*Bh with fp32 accumulators.
template <bool ADD_A2, bool RESID>
__global__ __launch_bounds__(256)
void hgemm_kernel(const float* __restrict__ A, const float* __restrict__ A2,
                  const __nv_bfloat16* __restrict__ Bth,
                  const __nv_bfloat16* __restrict__ Btl,
                  const float* __restrict__ bias,
                  const float* __restrict__ resid, float* __restrict__ C,
                  int M, int N, int K)
{
    // smem rows padded to 80B: 20i mod 32 banks -> conflict-free ldmatrix
    __shared__ __align__(16) uint8_t sAh[128 * 80];
    __shared__ __align__(16) uint8_t sAl[128 * 80];
    __shared__ __align__(16) uint8_t sBh[64 * 80];
    __shared__ __align__(16) uint8_t sBl[64 * 80];

    const int tid  = threadIdx.x;
    const int lane = tid & 31;
    const int wid  = tid >> 5;
    const int wm   = wid >> 1;         // 0..3
    const int wn   = wid & 1;          // 0..1
    const int bm   = blockIdx.x * 128;
    const int bn   = blockIdx.y * 64;

    const uint32_t uAh = smem_u32(sAh), uAl = smem_u32(sAl);
    const uint32_t uBh = smem_u32(sBh), uBl = smem_u32(sBl);

    // ldmatrix lane address patterns
    const int lrA = ((lane >> 3) & 1) * 8 + (lane & 7);
    const int lkA = (lane >> 4) * 8;
    const uint32_t aBaseH = uAh + (wm * 32 + lrA) * 80 + lkA * 2;
    const uint32_t aBaseL = uAl + (wm * 32 + lrA) * 80 + lkA * 2;
    const int lrB = (lane >> 4) * 8 + (lane & 7);
    const int lkB = ((lane >> 3) & 1) * 8;
    const uint32_t bBaseH = uBh + (wn * 32 + lrB) * 80 + lkB * 2;
    const uint32_t bBaseL = uBl + (wn * 32 + lrB) * 80 + lkB * 2;

    float acc[2][4][4];
#pragma unroll
    for (int t = 0; t < 2; t++)
#pragma unroll
        for (int u = 0; u < 4; u++)
#pragma unroll
            for (int i = 0; i < 4; i++) acc[t][u][i] = 0.f;

    // cooperative load indices
    const int brow = tid >> 2;          // 0..63
    const int bkg  = tid & 3;           // 4 x 8 bf16 (16B) per row

    for (int k0 = 0; k0 < K; k0 += 32) {
        // ---- stage gmem into regs ----
        float4 av[4];
#pragma unroll
        for (int j = 0; j < 4; j++) {
            const int gi = tid + j * 256;
            const int row = gi >> 3, kg = gi & 7;
            av[j] = *(const float4*)(A + (size_t)(bm + row) * K + k0 + kg * 4);
            if (ADD_A2) {
                float4 u = *(const float4*)(A2 + (size_t)(bm + row) * K + k0 + kg * 4);
                av[j].x += u.x; av[j].y += u.y; av[j].z += u.z; av[j].w += u.w;
            }
        }
        const uint4 bhv = *(const uint4*)(Bth + (size_t)(bn + brow) * K + k0 + bkg * 8);
        const uint4 blv = *(const uint4*)(Btl + (size_t)(bn + brow) * K + k0 + bkg * 8);

        __syncthreads();   // previous iter's compute done

        // ---- convert + store to smem ----
#pragma unroll
        for (int j = 0; j < 4; j++) {
            const int gi = tid + j * 256;
            const int row = gi >> 3, kg = gi & 7;
            const float4 v = av[j];
            const float hx = __bfloat162float(__float2bfloat16_rn(v.x));
            const float hy = __bfloat162float(__float2bfloat16_rn(v.y));
            const float hz = __bfloat162float(__float2bfloat16_rn(v.z));
            const float hw = __bfloat162float(__float2bfloat16_rn(v.w));
            *(uint2*)(sAh + row * 80 + kg * 8) =
                make_uint2(pack_bf16(v.x, v.y), pack_bf16(v.z, v.w));
            *(uint2*)(sAl + row * 80 + kg * 8) =
                make_uint2(pack_bf16(v.x - hx, v.y - hy),
                           pack_bf16(v.z - hz, v.w - hw));
        }
        *(uint4*)(sBh + brow * 80 + bkg * 16) = bhv;
        *(uint4*)(sBl + brow * 80 + bkg * 16) = blv;
        __syncthreads();

        // ---- compute: 2 k16 sub-steps ----
#pragma unroll
        for (int ks = 0; ks < 2; ks++) {
            const uint32_t ko = ks * 32;     // byte offset for k16 step
            uint32_t aH[2][4], aL[2][4], bH[4][2], bL[4][2];
            ldsm_x4(aH[0], aBaseH + ko);
            ldsm_x4(aH[1], aBaseH + 1280 + ko);
            ldsm_x4(aL[0], aBaseL + ko);
            ldsm_x4(aL[1], aBaseL + 1280 + ko);
            ldsm_x4(&bH[0][0], bBaseH + ko);
            ldsm_x4(&bH[2][0], bBaseH + 1280 + ko);
            ldsm_x4(&bL[0][0], bBaseL + ko);
            ldsm_x4(&bL[2][0], bBaseL + 1280 + ko);
#pragma unroll
            for (int t = 0; t < 2; t++)
#pragma unroll
                for (int u = 0; u < 4; u++) {
                    mma_bf16(acc[t][u], aH[t], bH[u]);
                    mma_bf16(acc[t][u], aH[t], bL[u]);
                    mma_bf16(acc[t][u], aL[t], bH[u]);
                }
        }
    }

    // ---- epilogue ----
    const int g = lane >> 2, tg = lane & 3;
#pragma unroll
    for (int t = 0; t < 2; t++)
#pragma unroll
        for (int u = 0; u < 4; u++) {
            const int row = bm + wm * 32 + t * 16 + g;
            const int col = bn + wn * 32 + u * 8 + tg * 2;
            const float2 bv = *(const float2*)(bias + col);
            float2 o0 = make_float2(acc[t][u][0] + bv.x, acc[t][u][1] + bv.y);
            float2 o1 = make_float2(acc[t][u][2] + bv.x, acc[t][u][3] + bv.y);
            if (RESID) {
                const float2 r0 = *(const float2*)(resid + (size_t)row * N + col);
                const float2 r1 = *(const float2*)(resid + (size_t)(row + 8) * N + col);
                o0.x += r0.x; o0.y += r0.y;
                o1.x += r1.x; o1.y += r1.y;
            }
            *(float2*)(C + (size_t)row * N + col) = o0;
            *(float2*)(C + (size_t)(row + 8) * N + col) = o1;
        }
}

// ---------------- sampling kernel (round-2 version) ------------------------
__global__ __launch_bounds__(256)
void sample_kernel(const float* __restrict__ refp, float* __restrict__ ms)
{
    __shared__ unsigned long long sm_iw[8][24][4];

    const int wslot = threadIdx.x >> 5;
    const int warp = blockIdx.x * 8 + wslot;
    const int lane = threadIdx.x & 31;
    const int h  = warp & 7;
    const int bq = warp >> 3;
    const int b  = bq >> 12;

    float a = -INFINITY;
    if (lane < 24) a = g_qa[(size_t)bq * NQA + NOFF + h * 24 + lane];
    float m = a;
#pragma unroll
    for (int s = 16; s; s >>= 1) m = fmaxf(m, __shfl_xor_sync(0xffffffffu, m, s));
    float e = (lane < 24) ? __expf(a - m) : 0.f;
    float ssum = e;
#pragma unroll
    for (int s = 16; s; s >>= 1) ssum += __shfl_xor_sync(0xffffffffu, ssum, s);
    const float aw = e / ssum;

    if (lane < 24) {
        const int l = lane >> 2;
        const int p = lane & 3;
        const int H = c_H[l], W = c_W[l], S = c_S[l];
        const size_t ob = (size_t)bq * NQA + (((h * NLVL + l) * NPT + p) << 1);
        const float offx = g_qa[ob + 0];
        const float offy = g_qa[ob + 1];
        const size_t rb = ((size_t)bq * NLVL + l) << 1;
        const float rx = refp[rb + 0];
        const float ry = refp[rb + 1];
        const float x = rx * (float)W + offx - 0.5f;
        const float y = ry * (float)H + offy - 0.5f;
        const float xf = floorf(x), yf = floorf(y);
        const float lx = x - xf, ly = y - yf;
        const int ix = (int)xf, iy = (int)yf;
        const bool vx0 = (ix     >= 0) && (ix     < W);
        const bool vx1 = (ix + 1 >= 0) && (ix + 1 < W);
        const bool vy0 = (iy     >= 0) && (iy     < H);
        const bool vy1 = (iy + 1 >= 0) && (iy + 1 < H);
        const int cx0 = min(max(ix, 0), W - 1);
        const int cx1 = min(max(ix + 1, 0), W - 1);
        const int cy0 = min(max(iy, 0), H - 1);
        const int cy1 = min(max(iy + 1, 0), H - 1);
        const int i00 = S + cy0 * W + cx0;
        const int i01 = S + cy0 * W + cx1;
        const int i10 = S + cy1 * W + cx0;
        const int i11 = S + cy1 * W + cx1;
        const float w00 = aw * (1.f - lx) * (1.f - ly) * (float)(vx0 && vy0);
        const float w01 = aw * lx         * (1.f - ly) * (float)(vx1 && vy0);
        const float w10 = aw * (1.f - lx) * ly         * (float)(vx0 && vy1);
        const float w11 = aw * lx         * ly         * (float)(vx1 && vy1);
        sm_iw[wslot][lane][0] =
            (unsigned long long)(unsigned)i00 | ((unsigned long long)__float_as_uint(w00) << 32);
        sm_iw[wslot][lane][1] =
            (unsigned long long)(unsigned)i01 | ((unsigned long long)__float_as_uint(w01) << 32);
        sm_iw[wslot][lane][2] =
            (unsigned long long)(unsigned)i10 | ((unsigned long long)__float_as_uint(w10) << 32);
        sm_iw[wslot][lane][3] =
            (unsigned long long)(unsigned)i11 | ((unsigned long long)__float_as_uint(w11) << 32);
    }
    __syncwarp();

    const int g  = lane >> 3;
    const int li = lane & 7;
    const float* __restrict__ vb =
        g_vproj + (size_t)b * NVAL * CDIM + h * DHEAD + li * 4;

    float4 acc = make_float4(0.f, 0.f, 0.f, 0.f);
#pragma unroll
    for (int j = 0; j < 24; j++) {
        const unsigned long long u = sm_iw[wslot][j][g];
        const int   idx = (int)(unsigned)(u & 0xffffffffu);
        const float w   = __uint_as_float((unsigned)(u >> 32));
        const float4 v = *(const float4*)(vb + (size_t)idx * CDIM);
        acc.x = fmaf(w, v.x, acc.x);
        acc.y = fmaf(w, v.y, acc.y);
        acc.z = fmaf(w, v.z, acc.z);
        acc.w = fmaf(w, v.w, acc.w);
    }
#pragma unroll
    for (int s = 8; s <= 16; s <<= 1) {
        acc.x += __shfl_xor_sync(0xffffffffu, acc.x, s);
        acc.y += __shfl_xor_sync(0xffffffffu, acc.y, s);
        acc.z += __shfl_xor_sync(0xffffffffu, acc.z, s);
        acc.w += __shfl_xor_sync(0xffffffffu, acc.w, s);
    }
    if (lane < 8)
        *(float4*)(ms + (size_t)bq * CDIM + h * DHEAD + lane * 4) = acc;
}

// ---------------- launch ----------------
extern "C" void kernel_launch(void* const* d_in, const int* in_sizes, int n_in,
                              void* d_out, int out_size)
{
    const float* query  = (const float*)d_in[0];
    const float* qpos   = (const float*)d_in[1];
    const float* value  = (const float*)d_in[2];
    const float* refp   = (const float*)d_in[3];
    const float* W_off  = (const float*)d_in[5];
    const float* b_off  = (const float*)d_in[6];
    const float* W_attn = (const float*)d_in[7];
    const float* b_attn = (const float*)d_in[8];
    const float* W_val  = (const float*)d_in[9];
    const float* b_val  = (const float*)d_in[10];
    const float* W_out  = (const float*)d_in[11];
    const float* b_out  = (const float*)d_in[12];
    float* out = (float*)d_out;

    float *vproj, *qa, *msb, *biasb;
    __nv_bfloat16 *wth, *wtl;
    cudaGetSymbolAddress((void**)&vproj, g_vproj);
    cudaGetSymbolAddress((void**)&qa,    g_qa);
    cudaGetSymbolAddress((void**)&msb,   g_ms);
    cudaGetSymbolAddress((void**)&biasb, g_bias);
    cudaGetSymbolAddress((void**)&wth,   g_Wt_hi);
    cudaGetSymbolAddress((void**)&wtl,   g_Wt_lo);

    const int MQ = BSZ * NQ;      // 32768
    const int MV = BSZ * NVAL;    // 86016

    // 0) transpose + bf16 hi/lo split of all weights, concat bias
    prep_w_kernel<<<NWT, 256>>>(W_val, b_val, W_off, b_off,
                                W_attn, b_attn, W_out, b_out);

    // 1) value projection: [MV,256] @ W_val -> g_vproj
    hgemm_kernel<false, false><<<dim3(MV / 128, CDIM / 64), 256>>>(
        value, nullptr, wth, wtl, biasb, nullptr, vproj, MV, CDIM, CDIM);

    // 2) fused offsets+attn: (query+qpos) @ [W_off|W_attn] -> g_qa [MQ,576]
    hgemm_kernel<true, false><<<dim3(MQ / 128, NQA / 64), 256>>>(
        query, qpos, wth + 256 * CDIM, wtl + 256 * CDIM, biasb + 256,
        nullptr, qa, MQ, NQA, CDIM);

    // 3) softmax + bilinear sampling -> g_ms [MQ,256]
    sample_kernel<<<(BSZ * NQ * NHEAD) / 8, 256>>>(refp, msb);

    // 4) output projection + residual -> out
    hgemm_kernel<false, true><<<dim3(MQ / 128, CDIM / 64), 256>>>(
        msb, nullptr, wth + 832 * CDIM, wtl + 832 * CDIM, biasb + 832,
        query, out, MQ, CDIM, CDIM);
}

// round 7
// speedup vs baseline: 2.8221x; 1.1302x over previous
#include <cuda_runtime.h>
#include <cuda_bf16.h>
#include <math.h>
#include <stdint.h>

// ---------------- problem constants (static per reference) ----------------
#define BSZ   8
#define NQ    4096
#define CDIM  256
#define NHEAD 8
#define NPT   4
#define NLVL  6
#define NVAL  10752
#define DHEAD 32
#define NOFF  384
#define NATT  192
#define NQA   576          // NOFF + NATT fused GEMM width
#define NWT   1088         // 256 (val) + 576 (off|attn) + 256 (out)
#define MQ    (BSZ * NQ)   // 32768
#define MV    (BSZ * NVAL) // 86016

// ---------------- device scratch (static, no allocation) ------------------
__device__ float g_vproj[(size_t)MV * CDIM];
__device__ float g_qa   [(size_t)MQ * NQA];            // [off(384) | attn(192)]
__device__ __nv_bfloat16 g_val_h[(size_t)MV * CDIM];   // value, bf16 hi
__device__ __nv_bfloat16 g_val_l[(size_t)MV * CDIM];   // value, bf16 lo
__device__ __nv_bfloat16 g_q_h  [(size_t)MQ * CDIM];   // query+qpos hi
__device__ __nv_bfloat16 g_q_l  [(size_t)MQ * CDIM];   // query+qpos lo
__device__ __nv_bfloat16 g_ms_h [(size_t)MQ * CDIM];   // deform-attn out hi
__device__ __nv_bfloat16 g_ms_l [(size_t)MQ * CDIM];   // deform-attn out lo
__device__ __nv_bfloat16 g_Wt_hi[NWT * CDIM];          // all weights^T hi
__device__ __nv_bfloat16 g_Wt_lo[NWT * CDIM];          // all weights^T lo
__device__ float g_bias[NWT];

__constant__ int c_H[NLVL] = {64, 32, 16, 64, 32, 16};
__constant__ int c_W[NLVL] = {64, 32, 16, 64, 32, 16};
__constant__ int c_S[NLVL] = {0, 4096, 5120, 5376, 9472, 10496};

// ---------------- small helpers -------------------------------------------
__device__ __forceinline__ uint32_t smem_u32(const void* p) {
    uint32_t a;
    asm("{ .reg .u64 t; cvta.to.shared.u64 t, %1; cvt.u32.u64 %0, t; }"
        : "=r"(a) : "l"(p));
    return a;
}
__device__ __forceinline__ void ldsm_x4(uint32_t* r, uint32_t addr) {
    asm volatile("ldmatrix.sync.aligned.m8n8.x4.shared.b16 {%0,%1,%2,%3}, [%4];"
                 : "=r"(r[0]), "=r"(r[1]), "=r"(r[2]), "=r"(r[3]) : "r"(addr));
}
__device__ __forceinline__ void mma_bf16(float* c, const uint32_t* a,
                                         const uint32_t* b) {
    asm volatile(
        "mma.sync.aligned.m16n8k16.row.col.f32.bf16.bf16.f32 "
        "{%0,%1,%2,%3}, {%4,%5,%6,%7}, {%8,%9}, {%0,%1,%2,%3};"
        : "+f"(c[0]), "+f"(c[1]), "+f"(c[2]), "+f"(c[3])
        : "r"(a[0]), "r"(a[1]), "r"(a[2]), "r"(a[3]), "r"(b[0]), "r"(b[1]));
}
__device__ __forceinline__ uint32_t pack_bf16(float x, float y) {
    __nv_bfloat162 t = __halves2bfloat162(__float2bfloat16_rn(x),
                                          __float2bfloat16_rn(y));
    return *(uint32_t*)&t;
}
__device__ __forceinline__ void cp16(uint32_t dst, const void* src) {
    asm volatile("cp.async.cg.shared.global [%0], [%1], 16;"
                 :: "r"(dst), "l"(src));
}
#define CP_COMMIT() asm volatile("cp.async.commit_group;" ::: "memory")
#define CP_WAIT(n)  asm volatile("cp.async.wait_group %0;" :: "n"(n) : "memory")

// ============== weight transpose + bf16 hi/lo split (one-time prep) ========
__global__ void prep_w_kernel(const float* __restrict__ W_val,
                              const float* __restrict__ b_val,
                              const float* __restrict__ W_off,
                              const float* __restrict__ b_off,
                              const float* __restrict__ W_attn,
                              const float* __restrict__ b_attn,
                              const float* __restrict__ W_out,
                              const float* __restrict__ b_out)
{
    const int n = blockIdx.x;
    const int k = threadIdx.x;
    float x, bb;
    if (n < 256)      { x = W_val[k * 256 + n];          bb = b_val[n]; }
    else if (n < 832) {
        const int m = n - 256;
        if (m < 384)  { x = W_off[k * 384 + m];          bb = b_off[m]; }
        else          { x = W_attn[k * 192 + (m - 384)]; bb = b_attn[m - 384]; }
    }
    else              { x = W_out[k * 256 + (n - 832)];  bb = b_out[n - 832]; }
    const __nv_bfloat16 hi = __float2bfloat16_rn(x);
    const __nv_bfloat16 lo = __float2bfloat16_rn(x - __bfloat162float(hi));
    g_Wt_hi[n * CDIM + k] = hi;
    g_Wt_lo[n * CDIM + k] = lo;
    if (k == 0) g_bias[n] = bb;
}

// ============== activation bf16 hi/lo split (streaming) =====================
// One thread per 4 contiguous floats.
template <bool ADD>
__global__ __launch_bounds__(256)
void prep_split_kernel(const float* __restrict__ A, const float* __restrict__ A2,
                       __nv_bfloat16* __restrict__ H, __nv_bfloat16* __restrict__ L)
{
    const size_t i4 = (size_t)blockIdx.x * 256 + threadIdx.x;
    float4 v = ((const float4*)A)[i4];
    if (ADD) {
        float4 u = ((const float4*)A2)[i4];
        v.x += u.x; v.y += u.y; v.z += u.z; v.w += u.w;
    }
    const float hx = __bfloat162float(__float2bfloat16_rn(v.x));
    const float hy = __bfloat162float(__float2bfloat16_rn(v.y));
    const float hz = __bfloat162float(__float2bfloat16_rn(v.z));
    const float hw = __bfloat162float(__float2bfloat16_rn(v.w));
    ((uint2*)H)[i4] = make_uint2(pack_bf16(v.x, v.y), pack_bf16(v.z, v.w));
    ((uint2*)L)[i4] = make_uint2(pack_bf16(v.x - hx, v.y - hy),
                                 pack_bf16(v.z - hz, v.w - hw));
}

// ============== bf16-split HMMA GEMM, cp.async double-buffered =============
// C[M,N] = A@B^T + bias (+resid);  A = Ah+Al (bf16 [M,K]), B = Bh+Bl ([N,K]).
// D = Ah*Bh + Ah*Bl + Al*Bh, fp32 accum. BM=128, BN=64, BK=32, 8 warps.
// Dynamic smem: 2 stages x (Ah 10240 | Al 10240 | Bh 5120 | Bl 5120) = 61440.
#define HG_STG   30720
#define HG_SMEM  61440

template <bool RESID>
__global__ __launch_bounds__(256)
void hgemm2_kernel(const __nv_bfloat16* __restrict__ Ath,
                   const __nv_bfloat16* __restrict__ Atl,
                   const __nv_bfloat16* __restrict__ Bth,
                   const __nv_bfloat16* __restrict__ Btl,
                   const float* __restrict__ bias,
                   const float* __restrict__ resid, float* __restrict__ C,
                   int M, int N, int K)
{
    extern __shared__ __align__(16) uint8_t smem[];
    const uint32_t uS = smem_u32(smem);

    const int tid  = threadIdx.x;
    const int lane = tid & 31;
    const int wid  = tid >> 5;
    const int wm   = wid >> 1;         // 0..3
    const int wn   = wid & 1;          // 0..1
    const int bm   = blockIdx.x * 128;
    const int bn   = blockIdx.y * 64;
    const int KT   = K >> 5;           // 8

    // ldmatrix lane offsets (relative to stage base)
    const int lrA = ((lane >> 3) & 1) * 8 + (lane & 7);
    const int lkA = (lane >> 4) * 8;
    const uint32_t offAh = (uint32_t)((wm * 32 + lrA) * 80 + lkA * 2);
    const uint32_t offAl = offAh + 10240u;
    const int lrB = (lane >> 4) * 8 + (lane & 7);
    const int lkB = ((lane >> 3) & 1) * 8;
    const uint32_t offBh = 20480u + (uint32_t)((wn * 32 + lrB) * 80 + lkB * 2);
    const uint32_t offBl = offBh + 5120u;

    // staging indices
    const int ar0 = tid >> 2, ac0 = tid & 3;            // j=0: rows 0..63
    const int ar1 = (tid + 256) >> 2;                   // j=1: rows 64..127
    const int br  = tid >> 2, bc = tid & 3;             // B rows 0..63

    float acc[2][4][4];
#pragma unroll
    for (int t = 0; t < 2; t++)
#pragma unroll
        for (int u = 0; u < 4; u++)
#pragma unroll
            for (int i = 0; i < 4; i++) acc[t][u][i] = 0.f;

    // ---- issue one stage of cp.async (6 x 16B per thread) ----
    auto issue = [&](int kt, int buf) {
        const int k0 = kt * 32;
        const uint32_t base = uS + buf * HG_STG;
        const size_t oa0 = (size_t)(bm + ar0) * K + k0 + ac0 * 8;
        const size_t oa1 = (size_t)(bm + ar1) * K + k0 + ac0 * 8;
        const size_t ob  = (size_t)(bn + br ) * K + k0 + bc  * 8;
        cp16(base +          ar0 * 80 + ac0 * 16, Ath + oa0);
        cp16(base +          ar1 * 80 + ac0 * 16, Ath + oa1);
        cp16(base + 10240u + ar0 * 80 + ac0 * 16, Atl + oa0);
        cp16(base + 10240u + ar1 * 80 + ac0 * 16, Atl + oa1);
        cp16(base + 20480u + br  * 80 + bc  * 16, Bth + ob);
        cp16(base + 25600u + br  * 80 + bc  * 16, Btl + ob);
        CP_COMMIT();
    };

    issue(0, 0);
    issue(1, 1);

#pragma unroll 1
    for (int kt = 0; kt < KT; kt++) {
        if (kt == KT - 1) { CP_WAIT(0); } else { CP_WAIT(1); }
        __syncthreads();

        const uint32_t sb = uS + (kt & 1) * HG_STG;
#pragma unroll
        for (int ks = 0; ks < 2; ks++) {
            const uint32_t ko = ks * 32;
            uint32_t aH[2][4], aL[2][4], bH[4][2], bL[4][2];
            ldsm_x4(aH[0], sb + offAh + ko);
            ldsm_x4(aH[1], sb + offAh + 1280 + ko);
            ldsm_x4(aL[0], sb + offAl + ko);
            ldsm_x4(aL[1], sb + offAl + 1280 + ko);
            ldsm_x4(&bH[0][0], sb + offBh + ko);
            ldsm_x4(&bH[2][0], sb + offBh + 1280 + ko);
            ldsm_x4(&bL[0][0], sb + offBl + ko);
            ldsm_x4(&bL[2][0], sb + offBl + 1280 + ko);
#pragma unroll
            for (int t = 0; t < 2; t++)
#pragma unroll
                for (int u = 0; u < 4; u++) {
                    mma_bf16(acc[t][u], aH[t], bH[u]);
                    mma_bf16(acc[t][u], aH[t], bL[u]);
                    mma_bf16(acc[t][u], aL[t], bH[u]);
                }
        }
        __syncthreads();
        if (kt + 2 < KT) issue(kt + 2, kt & 1);
    }

    // ---- epilogue (identical to round-6 verified mapping) ----
    const int g = lane >> 2, tg = lane & 3;
#pragma unroll
    for (int t = 0; t < 2; t++)
#pragma unroll
        for (int u = 0; u < 4; u++) {
            const int row = bm + wm * 32 + t * 16 + g;
            const int col = bn + wn * 32 + u * 8 + tg * 2;
            const float2 bv = *(const float2*)(bias + col);
            float2 o0 = make_float2(acc[t][u][0] + bv.x, acc[t][u][1] + bv.y);
            float2 o1 = make_float2(acc[t][u][2] + bv.x, acc[t][u][3] + bv.y);
            if (RESID) {
                const float2 r0 = *(const float2*)(resid + (size_t)row * N + col);
                const float2 r1 = *(const float2*)(resid + (size_t)(row + 8) * N + col);
                o0.x += r0.x; o0.y += r0.y;
                o1.x += r1.x; o1.y += r1.y;
            }
            *(float2*)(C + (size_t)row * N + col) = o0;
            *(float2*)(C + (size_t)(row + 8) * N + col) = o1;
        }
}

// ---------------- sampling kernel (round-2 core; bf16 hi/lo output) --------
__global__ __launch_bounds__(256)
void sample_kernel(const float* __restrict__ refp)
{
    __shared__ unsigned long long sm_iw[8][24][4];

    const int wslot = threadIdx.x >> 5;
    const int warp = blockIdx.x * 8 + wslot;
    const int lane = threadIdx.x & 31;
    const int h  = warp & 7;
    const int bq = warp >> 3;
    const int b  = bq >> 12;

    float a = -INFINITY;
    if (lane < 24) a = g_qa[(size_t)bq * NQA + NOFF + h * 24 + lane];
    float m = a;
#pragma unroll
    for (int s = 16; s; s >>= 1) m = fmaxf(m, __shfl_xor_sync(0xffffffffu, m, s));
    float e = (lane < 24) ? __expf(a - m) : 0.f;
    float ssum = e;
#pragma unroll
    for (int s = 16; s; s >>= 1) ssum += __shfl_xor_sync(0xffffffffu, ssum, s);
    const float aw = e / ssum;

    if (lane < 24) {
        const int l = lane >> 2;
        const int p = lane & 3;
        const int H = c_H[l], W = c_W[l], S = c_S[l];
        const size_t ob = (size_t)bq * NQA + (((h * NLVL + l) * NPT + p) << 1);
        const float offx = g_qa[ob + 0];
        const float offy = g_qa[ob + 1];
        const size_t rb = ((size_t)bq * NLVL + l) << 1;
        const float rx = refp[rb + 0];
        const float ry = refp[rb + 1];
        const float x = rx * (float)W + offx - 0.5f;
        const float y = ry * (float)H + offy - 0.5f;
        const float xf = floorf(x), yf = floorf(y);
        const float lx = x - xf, ly = y - yf;
        const int ix = (int)xf, iy = (int)yf;
        const bool vx0 = (ix     >= 0) && (ix     < W);
        const bool vx1 = (ix + 1 >= 0) && (ix + 1 < W);
        const bool vy0 = (iy     >= 0) && (iy     < H);
        const bool vy1 = (iy + 1 >= 0) && (iy + 1 < H);
        const int cx0 = min(max(ix, 0), W - 1);
        const int cx1 = min(max(ix + 1, 0), W - 1);
        const int cy0 = min(max(iy, 0), H - 1);
        const int cy1 = min(max(iy + 1, 0), H - 1);
        const int i00 = S + cy0 * W + cx0;
        const int i01 = S + cy0 * W + cx1;
        const int i10 = S + cy1 * W + cx0;
        const int i11 = S + cy1 * W + cx1;
        const float w00 = aw * (1.f - lx) * (1.f - ly) * (float)(vx0 && vy0);
        const float w01 = aw * lx         * (1.f - ly) * (float)(vx1 && vy0);
        const float w10 = aw * (1.f - lx) * ly         * (float)(vx0 && vy1);
        const float w11 = aw * lx         * ly         * (float)(vx1 && vy1);
        sm_iw[wslot][lane][0] =
            (unsigned long long)(unsigned)i00 | ((unsigned long long)__float_as_uint(w00) << 32);
        sm_iw[wslot][lane][1] =
            (unsigned long long)(unsigned)i01 | ((unsigned long long)__float_as_uint(w01) << 32);
        sm_iw[wslot][lane][2] =
            (unsigned long long)(unsigned)i10 | ((unsigned long long)__float_as_uint(w10) << 32);
        sm_iw[wslot][lane][3] =
            (unsigned long long)(unsigned)i11 | ((unsigned long long)__float_as_uint(w11) << 32);
    }
    __syncwarp();

    const int g  = lane >> 3;
    const int li = lane & 7;
    const float* __restrict__ vb =
        g_vproj + (size_t)b * NVAL * CDIM + h * DHEAD + li * 4;

    float4 acc = make_float4(0.f, 0.f, 0.f, 0.f);
#pragma unroll
    for (int j = 0; j < 24; j++) {
        const unsigned long long u = sm_iw[wslot][j][g];
        const int   idx = (int)(unsigned)(u & 0xffffffffu);
        const float w   = __uint_as_float((unsigned)(u >> 32));
        const float4 v = *(const float4*)(vb + (size_t)idx * CDIM);
        acc.x = fmaf(w, v.x, acc.x);
        acc.y = fmaf(w, v.y, acc.y);
        acc.z = fmaf(w, v.z, acc.z);
        acc.w = fmaf(w, v.w, acc.w);
    }
#pragma unroll
    for (int s = 8; s <= 16; s <<= 1) {
        acc.x += __shfl_xor_sync(0xffffffffu, acc.x, s);
        acc.y += __shfl_xor_sync(0xffffffffu, acc.y, s);
        acc.z += __shfl_xor_sync(0xffffffffu, acc.z, s);
        acc.w += __shfl_xor_sync(0xffffffffu, acc.w, s);
    }
    if (lane < 8) {
        const size_t o4 = ((size_t)bq * CDIM + h * DHEAD + lane * 4) >> 2;
        const float hx = __bfloat162float(__float2bfloat16_rn(acc.x));
        const float hy = __bfloat162float(__float2bfloat16_rn(acc.y));
        const float hz = __bfloat162float(__float2bfloat16_rn(acc.z));
        const float hw = __bfloat162float(__float2bfloat16_rn(acc.w));
        ((uint2*)g_ms_h)[o4] = make_uint2(pack_bf16(acc.x, acc.y),
                                          pack_bf16(acc.z, acc.w));
        ((uint2*)g_ms_l)[o4] = make_uint2(pack_bf16(acc.x - hx, acc.y - hy),
                                          pack_bf16(acc.z - hz, acc.w - hw));
    }
}

// ---------------- launch ----------------
extern "C" void kernel_launch(void* const* d_in, const int* in_sizes, int n_in,
                              void* d_out, int out_size)
{
    const float* query  = (const float*)d_in[0];
    const float* qpos   = (const float*)d_in[1];
    const float* value  = (const float*)d_in[2];
    const float* refp   = (const float*)d_in[3];
    const float* W_off  = (const float*)d_in[5];
    const float* b_off  = (const float*)d_in[6];
    const float* W_attn = (const float*)d_in[7];
    const float* b_attn = (const float*)d_in[8];
    const float* W_val  = (const float*)d_in[9];
    const float* b_val  = (const float*)d_in[10];
    const float* W_out  = (const float*)d_in[11];
    const float* b_out  = (const float*)d_in[12];
    float* out = (float*)d_out;

    float *vproj, *qa, *biasb;
    __nv_bfloat16 *wth, *wtl, *valh, *vall, *qh, *ql, *msh, *msl;
    cudaGetSymbolAddress((void**)&vproj, g_vproj);
    cudaGetSymbolAddress((void**)&qa,    g_qa);
    cudaGetSymbolAddress((void**)&biasb, g_bias);
    cudaGetSymbolAddress((void**)&wth,   g_Wt_hi);
    cudaGetSymbolAddress((void**)&wtl,   g_Wt_lo);
    cudaGetSymbolAddress((void**)&valh,  g_val_h);
    cudaGetSymbolAddress((void**)&vall,  g_val_l);
    cudaGetSymbolAddress((void**)&qh,    g_q_h);
    cudaGetSymbolAddress((void**)&ql,    g_q_l);
    cudaGetSymbolAddress((void**)&msh,   g_ms_h);
    cudaGetSymbolAddress((void**)&msl,   g_ms_l);

    static bool attr_done = false;
    if (!attr_done) {
        cudaFuncSetAttribute(hgemm2_kernel<false>,
                             cudaFuncAttributeMaxDynamicSharedMemorySize, HG_SMEM);
        cudaFuncSetAttribute(hgemm2_kernel<true>,
                             cudaFuncAttributeMaxDynamicSharedMemorySize, HG_SMEM);
        attr_done = true;
    }

    // 0) weight prep + activation splits
    prep_w_kernel<<<NWT, 256>>>(W_val, b_val, W_off, b_off,
                                W_attn, b_attn, W_out, b_out);
    prep_split_kernel<false><<<(MV * CDIM / 4) / 256, 256>>>(value, nullptr, valh, vall);
    prep_split_kernel<true ><<<(MQ * CDIM / 4) / 256, 256>>>(query, qpos, qh, ql);

    // 1) value projection: [MV,256] @ W_val -> g_vproj (fp32)
    hgemm2_kernel<false><<<dim3(MV / 128, CDIM / 64), 256, HG_SMEM>>>(
        valh, vall, wth, wtl, biasb, nullptr, vproj, MV, CDIM, CDIM);

    // 2) fused offsets+attn: q @ [W_off|W_attn] -> g_qa [MQ,576]
    hgemm2_kernel<false><<<dim3(MQ / 128, NQA / 64), 256, HG_SMEM>>>(
        qh, ql, wth + 256 * CDIM, wtl + 256 * CDIM, biasb + 256,
        nullptr, qa, MQ, NQA, CDIM);

    // 3) softmax + bilinear sampling -> g_ms hi/lo (bf16)
    sample_kernel<<<(MQ * NHEAD) / 8, 256>>>(refp);

    // 4) output projection + residual -> out
    hgemm2_kernel<true><<<dim3(MQ / 128, CDIM / 64), 256, HG_SMEM>>>(
        msh, msl, wth + 832 * CDIM, wtl + 832 * CDIM, biasb + 832,
        query, out, MQ, CDIM, CDIM);
}